// round 13
// baseline (speedup 1.0000x reference)
#include <cuda_runtime.h>
#include <cuda_bf16.h>
#include <cuda_fp16.h>
#include <cstdint>

// Problem constants
#define NTOK 8192
#define DDIM 1024
#define HDIM 4096
#define NEXP 8
#define TOPK 2
#define CAP  2048          // (TOPK*NTOK)/NEXP
#define SLOTS (TOPK*NTOK)  // 16384

// ---------------- scratch (__device__ globals: allocation-free) ----------------
__device__ float g_scores[NTOK * NEXP];
__device__ float g_topv[NTOK * TOPK];
__device__ int   g_topi[NTOK * TOPK];
__device__ int   g_pos[SLOTS];
__device__ int   g_s2t[NEXP * CAP];
__device__ int   g_ce[NEXP];
// fp16 operands; uint4 backing guarantees 16B alignment
__device__ uint4 g_xh_[(size_t)NTOK * DDIM / 8];          // x hi
__device__ uint4 g_xl_[(size_t)NTOK * DDIM / 8];          // x lo (exact residual)
__device__ uint4 g_w1h_[(size_t)NEXP * HDIM * DDIM / 8];  // [E][n=H][k=D] fp16(w1)
__device__ uint4 g_w2h_[(size_t)NEXP * DDIM * HDIM / 8];  // [E][n=D][k=H] fp16(w2)
__device__ uint4 g_hh_[(size_t)NEXP * CAP * HDIM / 8];    // h hi
__device__ uint4 g_hl_[(size_t)NEXP * CAP * HDIM / 8];    // h lo
__device__ float g_y[(size_t)NEXP * CAP * DDIM];

#define H16P(a) (( __half*)(a))
#define CH16P(a) ((const __half*)(a))

// ---------------- init ----------------
__global__ void init_kernel() {
    int i = blockIdx.x * blockDim.x + threadIdx.x;
    if (i < NEXP * CAP) g_s2t[i] = -1;
    if (i < NEXP)       g_ce[i]  = 0;
}

// ---------------- split x -> fp16 hi/lo ----------------
__global__ void split_x_kernel(const float* __restrict__ x) {
    int i = blockIdx.x * blockDim.x + threadIdx.x;
    const int NP = NTOK * DDIM / 2;
    if (i >= NP) return;
    float2 v = ((const float2*)x)[i];
    __half2 h = __floats2half2_rn(v.x, v.y);
    float rx = v.x - __half2float(__low2half(h));
    float ry = v.y - __half2float(__high2half(h));
    __half2 l = __floats2half2_rn(rx, ry);
    ((__half2*)g_xh_)[i] = h;
    ((__half2*)g_xl_)[i] = l;
}

// ---------------- transpose + convert weights: in [E][K][N] -> out [E][N][K] fp16 ----------------
template<bool IS_W1>
__global__ void tsplit_kernel(const float* __restrict__ in, int K, int N) {
    __half* oh = H16P(IS_W1 ? g_w1h_ : g_w2h_);
    __shared__ float t[32][33];
    int e = blockIdx.z;
    int n0 = blockIdx.x * 32, k0 = blockIdx.y * 32;
    const float* ine = in + (size_t)e * K * N;
    int tx = threadIdx.x, ty = threadIdx.y;
#pragma unroll
    for (int j = 0; j < 32; j += 8)
        t[ty + j][tx] = ine[(size_t)(k0 + ty + j) * N + n0 + tx];
    __syncthreads();
    size_t ob = (size_t)e * N * K;
#pragma unroll
    for (int j = 0; j < 32; j += 8) {
        float v = t[tx][ty + j];
        oh[ob + (size_t)(n0 + ty + j) * K + k0 + tx] = __float2half_rn(v);
    }
}

// ---------------- gate ----------------
__global__ void gate_kernel(const float* __restrict__ x, const float* __restrict__ wg) {
    int gwarp = (blockIdx.x * blockDim.x + threadIdx.x) >> 5;
    int lane  = threadIdx.x & 31;
    if (gwarp >= NTOK) return;
    const float* xr = x + (size_t)gwarp * DDIM;
    float acc[NEXP];
#pragma unroll
    for (int e = 0; e < NEXP; e++) acc[e] = 0.f;
#pragma unroll 4
    for (int i = 0; i < DDIM / 32; i++) {
        int d = lane + 32 * i;
        float xv = xr[d];
        const float* wr = wg + d * NEXP;
#pragma unroll
        for (int e = 0; e < NEXP; e++) acc[e] = fmaf(xv, wr[e], acc[e]);
    }
#pragma unroll
    for (int off = 16; off > 0; off >>= 1)
#pragma unroll
        for (int e = 0; e < NEXP; e++)
            acc[e] += __shfl_xor_sync(0xffffffffu, acc[e], off);

    if (lane == 0) {
        float m = acc[0];
#pragma unroll
        for (int e = 1; e < NEXP; e++) m = fmaxf(m, acc[e]);
        float p[NEXP]; float s = 0.f;
#pragma unroll
        for (int e = 0; e < NEXP; e++) { p[e] = expf(acc[e] - m); s += p[e]; }
        float inv = 1.f / s;
#pragma unroll
        for (int e = 0; e < NEXP; e++) { p[e] *= inv; g_scores[gwarp * NEXP + e] = p[e]; }
        int i1 = 0; float v1 = p[0];
#pragma unroll
        for (int e = 1; e < NEXP; e++) if (p[e] > v1) { v1 = p[e]; i1 = e; }
        int i2 = -1; float v2 = -1.f;
#pragma unroll
        for (int e = 0; e < NEXP; e++) if (e != i1 && p[e] > v2) { v2 = p[e]; i2 = e; }
        g_topv[gwarp * 2 + 0] = v1; g_topv[gwarp * 2 + 1] = v2;
        g_topi[gwarp * 2 + 0] = i1; g_topi[gwarp * 2 + 1] = i2;
        atomicAdd(&g_ce[i1], 1);
    }
}

// ---------------- routing ----------------
__global__ void route_kernel() {
    const int T = 512, PER = SLOTS / T;
    int t = threadIdx.x;
    int lane = t & 31, w = t >> 5;
    int base = t * PER;

    int cnt[NEXP];
#pragma unroll
    for (int e = 0; e < NEXP; e++) cnt[e] = 0;
    int myexp[PER];
#pragma unroll
    for (int i = 0; i < PER; i++) {
        int s = base + i;
        int slot = s >> 13;
        int n = s & (NTOK - 1);
        int e = g_topi[n * 2 + slot];
        myexp[i] = e;
        cnt[e]++;
    }
    int inc[NEXP];
#pragma unroll
    for (int e = 0; e < NEXP; e++) inc[e] = cnt[e];
#pragma unroll
    for (int o = 1; o < 32; o <<= 1) {
#pragma unroll
        for (int e = 0; e < NEXP; e++) {
            int v = __shfl_up_sync(0xffffffffu, inc[e], o);
            if (lane >= o) inc[e] += v;
        }
    }
    __shared__ int wtot[16][NEXP], wexcl[16][NEXP];
    if (lane == 31)
#pragma unroll
        for (int e = 0; e < NEXP; e++) wtot[w][e] = inc[e];
    __syncthreads();
    if (t == 0) {
        int run[NEXP];
#pragma unroll
        for (int e = 0; e < NEXP; e++) run[e] = 0;
        for (int ww = 0; ww < 16; ww++)
#pragma unroll
            for (int e = 0; e < NEXP; e++) { wexcl[ww][e] = run[e]; run[e] += wtot[ww][e]; }
    }
    __syncthreads();
    int off[NEXP];
#pragma unroll
    for (int e = 0; e < NEXP; e++) off[e] = wexcl[w][e] + inc[e] - cnt[e];
#pragma unroll
    for (int i = 0; i < PER; i++) {
        int e = myexp[i];
        int p = off[e]++;
        int s = base + i;
        g_pos[s] = p;
        if (p < CAP) {
            int n = s & (NTOK - 1);
            g_s2t[e * CAP + p] = n;
        }
    }
}

// ---------------- fp16x2 GEMM: 128x128, BK=32, ldmatrix, 3-stage, 1 sync/iter ----------------
#define BM 128
#define BN 128
#define BK 32
#define RPW 20   // uint32 words per row: 16 data (32 fp16) + 4 pad (pitch 80B, conflict-free LDSM)
#define NST 3
#define TSTRIDE (128 * RPW * 4)          // 10240 B per tensor-stage
#define AH_OFF(s) ((uint32_t)((s) * TSTRIDE))
#define AL_OFF(s) ((uint32_t)(NST * TSTRIDE + (s) * TSTRIDE))
#define BH_OFF(s) ((uint32_t)(2 * NST * TSTRIDE + (s) * TSTRIDE))
#define SMEM_DYN (3 * NST * TSTRIDE)     // 92160 B

__device__ __forceinline__ void cp16(uint32_t dst, const void* src, int bytes) {
    asm volatile("cp.async.cg.shared.global [%0], [%1], 16, %2;\n"
                 :: "r"(dst), "l"(src), "r"(bytes));
}
__device__ __forceinline__ void cp_commit() { asm volatile("cp.async.commit_group;\n" ::); }
__device__ __forceinline__ void cp_wait1()  { asm volatile("cp.async.wait_group 1;\n" ::); }
__device__ __forceinline__ void cp_wait0()  { asm volatile("cp.async.wait_group 0;\n" ::); }

__device__ __forceinline__ void mma_f16(float* d, const uint32_t* a, const uint32_t* b) {
    asm volatile(
        "mma.sync.aligned.m16n8k16.row.col.f32.f16.f16.f32 "
        "{%0,%1,%2,%3}, {%4,%5,%6,%7}, {%8,%9}, {%0,%1,%2,%3};\n"
        : "+f"(d[0]), "+f"(d[1]), "+f"(d[2]), "+f"(d[3])
        : "r"(a[0]), "r"(a[1]), "r"(a[2]), "r"(a[3]), "r"(b[0]), "r"(b[1]));
}
__device__ __forceinline__ void ldsm4(uint32_t* r, uint32_t addr) {
    asm volatile("ldmatrix.sync.aligned.m8n8.x4.shared.b16 {%0,%1,%2,%3}, [%4];"
                 : "=r"(r[0]), "=r"(r[1]), "=r"(r[2]), "=r"(r[3]) : "r"(addr));
}

// PHASE1: A = gather(xh/xl), B = fp16(w1) [E][H][D]; out g_hh/g_hl (relu+bias+split)
// PHASE2: A = g_hh/g_hl,     B = fp16(w2) [E][D][H]; out g_y (+bias)
template<int KD, int ND, bool PHASE1>
__global__ void __launch_bounds__(256, 2) gemm_kernel(const float* __restrict__ bias)
{
    extern __shared__ char smraw[];
    const uint32_t sbase = (uint32_t)__cvta_generic_to_shared(smraw);
    const int e  = blockIdx.z;
    const int m0 = blockIdx.y * BM;
    const int n0 = blockIdx.x * BN;
    const float* be = bias + (size_t)e * ND;
    const int tid = threadIdx.x;

    // ---- loader: 512 chunks of 16B per tensor per stage; 2 per thread ----
    const __half *asrcH[2], *asrcL[2], *bsrcH[2];
    int aok[2]; uint32_t sdst[2];
#pragma unroll
    for (int i = 0; i < 2; i++) {
        int c = tid + i * 256;
        int row = c >> 2, g = c & 3;
        sdst[i] = (uint32_t)(row * 80 + g * 16);
        if (PHASE1) {
            int tok = g_s2t[e * CAP + m0 + row];
            aok[i] = (tok >= 0) ? 16 : 0;
            size_t ao = (tok >= 0) ? ((size_t)tok * KD + g * 8) : 0;
            asrcH[i] = CH16P(g_xh_) + ao;
            asrcL[i] = CH16P(g_xl_) + ao;
        } else {
            aok[i] = 16;
            size_t ao = (size_t)(e * CAP + m0 + row) * KD + g * 8;
            asrcH[i] = CH16P(g_hh_) + ao;
            asrcL[i] = CH16P(g_hl_) + ao;
        }
        size_t bo = (size_t)e * ND * KD + (size_t)(n0 + row) * KD + g * 8;
        bsrcH[i] = CH16P(PHASE1 ? g_w1h_ : g_w2h_) + bo;
    }

    auto load_stage = [&](int buf, int kt) {
        size_t ko = (size_t)kt * BK;
#pragma unroll
        for (int i = 0; i < 2; i++) {
            cp16(sbase + AH_OFF(buf) + sdst[i], asrcH[i] + ko, aok[i]);
            cp16(sbase + AL_OFF(buf) + sdst[i], asrcL[i] + ko, aok[i]);
            cp16(sbase + BH_OFF(buf) + sdst[i], bsrcH[i] + ko, 16);
        }
        cp_commit();
    };

    // ---- warp tiling: 2x4 warps, each 64x32 ----
    const int warp = tid >> 5, lane = tid & 31;
    const int wm = warp >> 2, wn = warp & 3;
    const int mb = wm * 64, nb = wn * 32;
    const int lr = lane >> 2, lc = lane & 3;

    const uint32_t a_lane = (uint32_t)((mb + (lane & 15)) * 80 + ((lane >> 4) & 1) * 16);
    const uint32_t b_lane0 = (uint32_t)((nb + ((lane >> 4) & 1) * 8 + (lane & 7)) * 80
                                        + ((lane >> 3) & 1) * 16);

    float acc[4][4][4];
#pragma unroll
    for (int mi = 0; mi < 4; mi++)
#pragma unroll
        for (int ni = 0; ni < 4; ni++)
#pragma unroll
            for (int r = 0; r < 4; r++) acc[mi][ni][r] = 0.f;

    const int KT = KD / BK;
    load_stage(0, 0);
    load_stage(1, 1);

    for (int kt = 0; kt < KT; kt++) {
        // wait for stage kt (pending groups before this iter's prefetch: kt, kt+1)
        if (kt + 1 < KT) cp_wait1();
        else             cp_wait0();
        __syncthreads();   // also protects stage (kt+2)%3 (consumed in iter kt-1)
        if (kt + 2 < KT) load_stage((kt + 2) % NST, kt + 2);

        int buf = kt % NST;
        const uint32_t ah_s = sbase + AH_OFF(buf);
        const uint32_t al_s = sbase + AL_OFF(buf);
        const uint32_t bh_s = sbase + BH_OFF(buf);

#pragma unroll
        for (int ks = 0; ks < 2; ks++) {
            const uint32_t ksb = (uint32_t)(ks * 32);
            uint32_t bh[4][2];
            ldsm4(&bh[0][0], bh_s + ksb + b_lane0);
            ldsm4(&bh[2][0], bh_s + ksb + b_lane0 + 16 * 80);
            uint32_t af[4][4];
            // lo pass
#pragma unroll
            for (int mi = 0; mi < 4; mi++)
                ldsm4(af[mi], al_s + ksb + a_lane + (uint32_t)(mi * 16 * 80));
#pragma unroll
            for (int mi = 0; mi < 4; mi++)
#pragma unroll
                for (int ni = 0; ni < 4; ni++)
                    mma_f16(acc[mi][ni], af[mi], bh[ni]);
            // hi pass (reuse af regs)
#pragma unroll
            for (int mi = 0; mi < 4; mi++)
                ldsm4(af[mi], ah_s + ksb + a_lane + (uint32_t)(mi * 16 * 80));
#pragma unroll
            for (int mi = 0; mi < 4; mi++)
#pragma unroll
                for (int ni = 0; ni < 4; ni++)
                    mma_f16(acc[mi][ni], af[mi], bh[ni]);
        }
    }

    // ---- epilogue ----
#pragma unroll
    for (int mi = 0; mi < 4; mi++) {
        int r = m0 + mb + mi * 16 + lr;
#pragma unroll
        for (int ni = 0; ni < 4; ni++) {
            int cb = n0 + nb + ni * 8 + 2 * lc;
            float b0 = be[cb], b1 = be[cb + 1];
            float v0 = acc[mi][ni][0] + b0, v1 = acc[mi][ni][1] + b1;
            float v2 = acc[mi][ni][2] + b0, v3 = acc[mi][ni][3] + b1;
            if (PHASE1) {
                v0 = fmaxf(v0, 0.f); v1 = fmaxf(v1, 0.f);
                v2 = fmaxf(v2, 0.f); v3 = fmaxf(v3, 0.f);
                size_t s0 = (size_t)(e * CAP + r) * HDIM + cb;
                size_t s1 = (size_t)(e * CAP + r + 8) * HDIM + cb;
                __half2 h0 = __floats2half2_rn(v0, v1);
                __half2 h1 = __floats2half2_rn(v2, v3);
                __half2 l0 = __floats2half2_rn(v0 - __half2float(__low2half(h0)),
                                               v1 - __half2float(__high2half(h0)));
                __half2 l1 = __floats2half2_rn(v2 - __half2float(__low2half(h1)),
                                               v3 - __half2float(__high2half(h1)));
                *(__half2*)(H16P(g_hh_) + s0) = h0;
                *(__half2*)(H16P(g_hh_) + s1) = h1;
                *(__half2*)(H16P(g_hl_) + s0) = l0;
                *(__half2*)(H16P(g_hl_) + s1) = l1;
            } else {
                float* Ce = g_y + (size_t)e * CAP * DDIM;
                *(float2*)&Ce[(size_t)r * DDIM + cb]       = make_float2(v0, v1);
                *(float2*)&Ce[(size_t)(r + 8) * DDIM + cb] = make_float2(v2, v3);
            }
        }
    }
}

// ---------------- combine ----------------
__global__ void combine_kernel(float* __restrict__ out) {
    int n = blockIdx.x, tid = threadIdx.x;
    float4 acc = make_float4(0.f, 0.f, 0.f, 0.f);
#pragma unroll
    for (int slot = 0; slot < TOPK; slot++) {
        int p = g_pos[slot * NTOK + n];
        if (p < CAP) {
            float v = g_topv[n * 2 + slot];
            int e = g_topi[n * 2 + slot];
            const float4* row = (const float4*)(g_y + (size_t)(e * CAP + p) * DDIM);
            float4 f = row[tid];
            acc.x += v * f.x; acc.y += v * f.y; acc.z += v * f.z; acc.w += v * f.w;
        }
    }
    ((float4*)(out + (size_t)n * DDIM))[tid] = acc;
}

// ---------------- aux loss ----------------
__global__ void aux_kernel(float* __restrict__ out, int out_size) {
    __shared__ float s[256];
    int tid = threadIdx.x;
    float p[NEXP];
#pragma unroll
    for (int e = 0; e < NEXP; e++) p[e] = 0.f;
    for (int i = tid; i < NTOK; i += 256)
#pragma unroll
        for (int e = 0; e < NEXP; e++) p[e] += g_scores[i * NEXP + e];

    float total = 0.f;
#pragma unroll
    for (int e = 0; e < NEXP; e++) {
        s[tid] = p[e];
        __syncthreads();
        for (int st = 128; st > 0; st >>= 1) {
            if (tid < st) s[tid] += s[tid + st];
            __syncthreads();
        }
        if (tid == 0) {
            float me = s[0] / (float)NTOK;
            float ce = (float)g_ce[e] / (float)NTOK;
            total += me * ce;
        }
        __syncthreads();
    }
    if (tid == 0) {
        float laux = (float)NEXP * total;
        for (long i = (long)NTOK * DDIM; i < (long)out_size; i++) out[i] = laux;
    }
}

// ---------------- launch ----------------
extern "C" void kernel_launch(void* const* d_in, const int* in_sizes, int n_in,
                              void* d_out, int out_size) {
    const float* x    = (const float*)d_in[0];
    const float* wg   = (const float*)d_in[1];
    const float* fc1w = (const float*)d_in[2];
    const float* fc1b = (const float*)d_in[3];
    const float* fc2w = (const float*)d_in[4];
    const float* fc2b = (const float*)d_in[5];
    float* out = (float*)d_out;
    (void)in_sizes; (void)n_in;

    cudaFuncSetAttribute(gemm_kernel<DDIM, HDIM, true >,
                         cudaFuncAttributeMaxDynamicSharedMemorySize, SMEM_DYN);
    cudaFuncSetAttribute(gemm_kernel<HDIM, DDIM, false>,
                         cudaFuncAttributeMaxDynamicSharedMemorySize, SMEM_DYN);

    init_kernel<<<(NEXP * CAP + 255) / 256, 256>>>();
    split_x_kernel<<<(NTOK * DDIM / 2 + 255) / 256, 256>>>(x);
    tsplit_kernel<true ><<<dim3(HDIM / 32, DDIM / 32, NEXP), dim3(32, 8)>>>(fc1w, DDIM, HDIM);
    tsplit_kernel<false><<<dim3(DDIM / 32, HDIM / 32, NEXP), dim3(32, 8)>>>(fc2w, HDIM, DDIM);
    gate_kernel<<<NTOK / 8, 256>>>(x, wg);
    route_kernel<<<1, 512>>>();
    gemm_kernel<DDIM, HDIM, true ><<<dim3(HDIM / BN, CAP / BM, NEXP), 256, SMEM_DYN>>>(fc1b);
    gemm_kernel<HDIM, DDIM, false><<<dim3(DDIM / BN, CAP / BM, NEXP), 256, SMEM_DYN>>>(fc2b);
    combine_kernel<<<NTOK, 256>>>(out);
    aux_kernel<<<1, 256>>>(out, out_size);
}

// round 14
// speedup vs baseline: 1.0231x; 1.0231x over previous
#include <cuda_runtime.h>
#include <cuda_bf16.h>
#include <cuda_fp16.h>
#include <cstdint>

// Problem constants
#define NTOK 8192
#define DDIM 1024
#define HDIM 4096
#define NEXP 8
#define TOPK 2
#define CAP  2048          // (TOPK*NTOK)/NEXP
#define SLOTS (TOPK*NTOK)  // 16384

// ---------------- scratch (__device__ globals: allocation-free) ----------------
__device__ float g_scores[NTOK * NEXP];
__device__ float g_topv[NTOK * TOPK];
__device__ int   g_topi[NTOK * TOPK];
__device__ int   g_pos[SLOTS];
__device__ int   g_s2t[NEXP * CAP];
__device__ float g_s2w[NEXP * CAP];     // gate weight per expert slot
__device__ int   g_ce[NEXP];
// fp16 operands; uint4 backing guarantees 16B alignment
__device__ uint4 g_xh_[(size_t)NTOK * DDIM / 8];          // x hi
__device__ uint4 g_xl_[(size_t)NTOK * DDIM / 8];          // x lo (exact residual)
__device__ uint4 g_w1h_[(size_t)NEXP * HDIM * DDIM / 8];  // [E][n=H][k=D] fp16(w1)
__device__ uint4 g_w2h_[(size_t)NEXP * DDIM * HDIM / 8];  // [E][n=D][k=H] fp16(w2)
__device__ uint4 g_hh_[(size_t)NEXP * CAP * HDIM / 8];    // h hi
__device__ uint4 g_hl_[(size_t)NEXP * CAP * HDIM / 8];    // h lo

#define H16P(a) (( __half*)(a))
#define CH16P(a) ((const __half*)(a))

// ---------------- init: s2t/ce reset + zero out[0 .. N*D) ----------------
__global__ void init_kernel(float* __restrict__ out) {
    int i = blockIdx.x * blockDim.x + threadIdx.x;
    if (i < NEXP * CAP) g_s2t[i] = -1;
    if (i < NEXP)       g_ce[i]  = 0;
    if (i < NTOK * DDIM / 4)
        ((float4*)out)[i] = make_float4(0.f, 0.f, 0.f, 0.f);
}

// ---------------- split x -> fp16 hi/lo ----------------
__global__ void split_x_kernel(const float* __restrict__ x) {
    int i = blockIdx.x * blockDim.x + threadIdx.x;
    const int NP = NTOK * DDIM / 2;
    if (i >= NP) return;
    float2 v = ((const float2*)x)[i];
    __half2 h = __floats2half2_rn(v.x, v.y);
    float rx = v.x - __half2float(__low2half(h));
    float ry = v.y - __half2float(__high2half(h));
    __half2 l = __floats2half2_rn(rx, ry);
    ((__half2*)g_xh_)[i] = h;
    ((__half2*)g_xl_)[i] = l;
}

// ---------------- transpose + convert weights: in [E][K][N] -> out [E][N][K] fp16 ----------------
// half2-vectorized writes (k pairs) for full-sector coalescing.
template<bool IS_W1>
__global__ void tsplit_kernel(const float* __restrict__ in, int K, int N) {
    __half* oh = H16P(IS_W1 ? g_w1h_ : g_w2h_);
    __shared__ float t[32][33];
    int e = blockIdx.z;
    int n0 = blockIdx.x * 32, k0 = blockIdx.y * 32;
    const float* ine = in + (size_t)e * K * N;
    int tid = threadIdx.x;
    // load 32x32 tile: t[k][n]
#pragma unroll
    for (int i = 0; i < 4; i++) {
        int idx = tid + i * 256;
        int k = idx >> 5, n = idx & 31;
        t[k][n] = ine[(size_t)(k0 + k) * N + n0 + n];
    }
    __syncthreads();
    // write transposed, half2 per store
    size_t ob = (size_t)e * N * K;
#pragma unroll
    for (int i = 0; i < 2; i++) {
        int idx = tid + i * 256;
        int n = idx >> 4;            // 0..31
        int kp = idx & 15;           // k pair
        int k = 2 * kp;
        __half2 v = __floats2half2_rn(t[k][n], t[k + 1][n]);
        *(__half2*)(oh + ob + (size_t)(n0 + n) * K + k0 + k) = v;
    }
}

// ---------------- gate ----------------
__global__ void gate_kernel(const float* __restrict__ x, const float* __restrict__ wg) {
    int gwarp = (blockIdx.x * blockDim.x + threadIdx.x) >> 5;
    int lane  = threadIdx.x & 31;
    if (gwarp >= NTOK) return;
    const float* xr = x + (size_t)gwarp * DDIM;
    float acc[NEXP];
#pragma unroll
    for (int e = 0; e < NEXP; e++) acc[e] = 0.f;
#pragma unroll 4
    for (int i = 0; i < DDIM / 32; i++) {
        int d = lane + 32 * i;
        float xv = xr[d];
        const float* wr = wg + d * NEXP;
#pragma unroll
        for (int e = 0; e < NEXP; e++) acc[e] = fmaf(xv, wr[e], acc[e]);
    }
#pragma unroll
    for (int off = 16; off > 0; off >>= 1)
#pragma unroll
        for (int e = 0; e < NEXP; e++)
            acc[e] += __shfl_xor_sync(0xffffffffu, acc[e], off);

    if (lane == 0) {
        float m = acc[0];
#pragma unroll
        for (int e = 1; e < NEXP; e++) m = fmaxf(m, acc[e]);
        float p[NEXP]; float s = 0.f;
#pragma unroll
        for (int e = 0; e < NEXP; e++) { p[e] = expf(acc[e] - m); s += p[e]; }
        float inv = 1.f / s;
#pragma unroll
        for (int e = 0; e < NEXP; e++) { p[e] *= inv; g_scores[gwarp * NEXP + e] = p[e]; }
        int i1 = 0; float v1 = p[0];
#pragma unroll
        for (int e = 1; e < NEXP; e++) if (p[e] > v1) { v1 = p[e]; i1 = e; }
        int i2 = -1; float v2 = -1.f;
#pragma unroll
        for (int e = 0; e < NEXP; e++) if (e != i1 && p[e] > v2) { v2 = p[e]; i2 = e; }
        g_topv[gwarp * 2 + 0] = v1; g_topv[gwarp * 2 + 1] = v2;
        g_topi[gwarp * 2 + 0] = i1; g_topi[gwarp * 2 + 1] = i2;
        atomicAdd(&g_ce[i1], 1);
    }
}

// ---------------- routing ----------------
__global__ void route_kernel() {
    const int T = 512, PER = SLOTS / T;
    int t = threadIdx.x;
    int lane = t & 31, w = t >> 5;
    int base = t * PER;

    int cnt[NEXP];
#pragma unroll
    for (int e = 0; e < NEXP; e++) cnt[e] = 0;
    int myexp[PER];
#pragma unroll
    for (int i = 0; i < PER; i++) {
        int s = base + i;
        int slot = s >> 13;
        int n = s & (NTOK - 1);
        int e = g_topi[n * 2 + slot];
        myexp[i] = e;
        cnt[e]++;
    }
    int inc[NEXP];
#pragma unroll
    for (int e = 0; e < NEXP; e++) inc[e] = cnt[e];
#pragma unroll
    for (int o = 1; o < 32; o <<= 1) {
#pragma unroll
        for (int e = 0; e < NEXP; e++) {
            int v = __shfl_up_sync(0xffffffffu, inc[e], o);
            if (lane >= o) inc[e] += v;
        }
    }
    __shared__ int wtot[16][NEXP], wexcl[16][NEXP];
    if (lane == 31)
#pragma unroll
        for (int e = 0; e < NEXP; e++) wtot[w][e] = inc[e];
    __syncthreads();
    if (t == 0) {
        int run[NEXP];
#pragma unroll
        for (int e = 0; e < NEXP; e++) run[e] = 0;
        for (int ww = 0; ww < 16; ww++)
#pragma unroll
            for (int e = 0; e < NEXP; e++) { wexcl[ww][e] = run[e]; run[e] += wtot[ww][e]; }
    }
    __syncthreads();
    int off[NEXP];
#pragma unroll
    for (int e = 0; e < NEXP; e++) off[e] = wexcl[w][e] + inc[e] - cnt[e];
#pragma unroll
    for (int i = 0; i < PER; i++) {
        int e = myexp[i];
        int p = off[e]++;
        int s = base + i;
        g_pos[s] = p;
        if (p < CAP) {
            int slot = s >> 13;
            int n = s & (NTOK - 1);
            g_s2t[e * CAP + p] = n;
            g_s2w[e * CAP + p] = g_topv[n * 2 + slot];
        }
    }
}

// ---------------- fp16x2 GEMM: 128x128 tile, BK=32, ldmatrix, 2-stage (R10) ----------------
#define BM 128
#define BN 128
#define BK 32
#define RPW 20   // uint32 words per row: 16 data (32 fp16) + 4 pad (pitch 80B, conflict-free LDSM)
#define TSTRIDE (128 * RPW * 4)          // 10240 B per tensor-stage
#define AH_OFF(s) ((uint32_t)((s) * TSTRIDE))
#define AL_OFF(s) ((uint32_t)(2 * TSTRIDE + (s) * TSTRIDE))
#define BH_OFF(s) ((uint32_t)(4 * TSTRIDE + (s) * TSTRIDE))
#define SMEM_DYN (6 * TSTRIDE)           // 61440 B

__device__ __forceinline__ void cp16(uint32_t dst, const void* src, int bytes) {
    asm volatile("cp.async.cg.shared.global [%0], [%1], 16, %2;\n"
                 :: "r"(dst), "l"(src), "r"(bytes));
}
__device__ __forceinline__ void cp_commit() { asm volatile("cp.async.commit_group;\n" ::); }
__device__ __forceinline__ void cp_wait1()  { asm volatile("cp.async.wait_group 1;\n" ::); }
__device__ __forceinline__ void cp_wait0()  { asm volatile("cp.async.wait_group 0;\n" ::); }

__device__ __forceinline__ void mma_f16(float* d, const uint32_t* a, const uint32_t* b) {
    asm volatile(
        "mma.sync.aligned.m16n8k16.row.col.f32.f16.f16.f32 "
        "{%0,%1,%2,%3}, {%4,%5,%6,%7}, {%8,%9}, {%0,%1,%2,%3};\n"
        : "+f"(d[0]), "+f"(d[1]), "+f"(d[2]), "+f"(d[3])
        : "r"(a[0]), "r"(a[1]), "r"(a[2]), "r"(a[3]), "r"(b[0]), "r"(b[1]));
}
__device__ __forceinline__ void ldsm4(uint32_t* r, uint32_t addr) {
    asm volatile("ldmatrix.sync.aligned.m8n8.x4.shared.b16 {%0,%1,%2,%3}, [%4];"
                 : "=r"(r[0]), "=r"(r[1]), "=r"(r[2]), "=r"(r[3]) : "r"(addr));
}

// PHASE1: A = gather(xh/xl), B = fp16(w1) [E][H][D]; out g_hh/g_hl (relu+bias+split)
// PHASE2: A = g_hh/g_hl,     B = fp16(w2) [E][D][H]; epilogue scatter-atomicAdd into out
template<int KD, int ND, bool PHASE1>
__global__ void __launch_bounds__(256, 2) gemm_kernel(const float* __restrict__ bias,
                                                      float* __restrict__ out)
{
    extern __shared__ char smraw[];
    const uint32_t sbase = (uint32_t)__cvta_generic_to_shared(smraw);
    const int e  = blockIdx.z;
    const int m0 = blockIdx.y * BM;
    const int n0 = blockIdx.x * BN;
    const float* be = bias + (size_t)e * ND;
    const int tid = threadIdx.x;

    // ---- loader: 512 chunks of 16B per tensor per stage; 2 per thread ----
    const __half *asrcH[2], *asrcL[2], *bsrcH[2];
    int aok[2]; uint32_t sdst[2];
#pragma unroll
    for (int i = 0; i < 2; i++) {
        int c = tid + i * 256;
        int row = c >> 2, g = c & 3;
        sdst[i] = (uint32_t)(row * 80 + g * 16);
        if (PHASE1) {
            int tok = g_s2t[e * CAP + m0 + row];
            aok[i] = (tok >= 0) ? 16 : 0;
            size_t ao = (tok >= 0) ? ((size_t)tok * KD + g * 8) : 0;
            asrcH[i] = CH16P(g_xh_) + ao;
            asrcL[i] = CH16P(g_xl_) + ao;
        } else {
            aok[i] = 16;
            size_t ao = (size_t)(e * CAP + m0 + row) * KD + g * 8;
            asrcH[i] = CH16P(g_hh_) + ao;
            asrcL[i] = CH16P(g_hl_) + ao;
        }
        size_t bo = (size_t)e * ND * KD + (size_t)(n0 + row) * KD + g * 8;
        bsrcH[i] = CH16P(PHASE1 ? g_w1h_ : g_w2h_) + bo;
    }

    auto load_stage = [&](int buf, int kt) {
        size_t ko = (size_t)kt * BK;
#pragma unroll
        for (int i = 0; i < 2; i++) {
            cp16(sbase + AH_OFF(buf) + sdst[i], asrcH[i] + ko, aok[i]);
            cp16(sbase + AL_OFF(buf) + sdst[i], asrcL[i] + ko, aok[i]);
            cp16(sbase + BH_OFF(buf) + sdst[i], bsrcH[i] + ko, 16);
        }
        cp_commit();
    };

    // ---- warp tiling: 2x4 warps, each 64x32 ----
    const int warp = tid >> 5, lane = tid & 31;
    const int wm = warp >> 2, wn = warp & 3;
    const int mb = wm * 64, nb = wn * 32;
    const int lr = lane >> 2, lc = lane & 3;

    const uint32_t a_lane = (uint32_t)((mb + (lane & 15)) * 80 + ((lane >> 4) & 1) * 16);
    const uint32_t b_lane0 = (uint32_t)((nb + ((lane >> 4) & 1) * 8 + (lane & 7)) * 80
                                        + ((lane >> 3) & 1) * 16);

    float acc[4][4][4];
#pragma unroll
    for (int mi = 0; mi < 4; mi++)
#pragma unroll
        for (int ni = 0; ni < 4; ni++)
#pragma unroll
            for (int r = 0; r < 4; r++) acc[mi][ni][r] = 0.f;

    const int KT = KD / BK;
    load_stage(0, 0);

    for (int kt = 0; kt < KT; kt++) {
        int buf = kt & 1;
        if (kt + 1 < KT) { load_stage(buf ^ 1, kt + 1); cp_wait1(); }
        else             { cp_wait0(); }
        __syncthreads();

        const uint32_t ah_s = sbase + AH_OFF(buf);
        const uint32_t al_s = sbase + AL_OFF(buf);
        const uint32_t bh_s = sbase + BH_OFF(buf);

#pragma unroll
        for (int ks = 0; ks < 2; ks++) {
            const uint32_t ksb = (uint32_t)(ks * 32);
            uint32_t bh[4][2];
            ldsm4(&bh[0][0], bh_s + ksb + b_lane0);
            ldsm4(&bh[2][0], bh_s + ksb + b_lane0 + 16 * 80);
            uint32_t af[4][4];
            // lo pass
#pragma unroll
            for (int mi = 0; mi < 4; mi++)
                ldsm4(af[mi], al_s + ksb + a_lane + (uint32_t)(mi * 16 * 80));
#pragma unroll
            for (int mi = 0; mi < 4; mi++)
#pragma unroll
                for (int ni = 0; ni < 4; ni++)
                    mma_f16(acc[mi][ni], af[mi], bh[ni]);
            // hi pass (reuse af regs)
#pragma unroll
            for (int mi = 0; mi < 4; mi++)
                ldsm4(af[mi], ah_s + ksb + a_lane + (uint32_t)(mi * 16 * 80));
#pragma unroll
            for (int mi = 0; mi < 4; mi++)
#pragma unroll
                for (int ni = 0; ni < 4; ni++)
                    mma_f16(acc[mi][ni], af[mi], bh[ni]);
        }
        __syncthreads();
    }

    // ---- epilogue ----
#pragma unroll
    for (int mi = 0; mi < 4; mi++) {
        int r = m0 + mb + mi * 16 + lr;       // row within expert buffer
        int tok0 = 0, tok1 = 0; float w0 = 0.f, w1 = 0.f;
        if (!PHASE1) {
            tok0 = g_s2t[e * CAP + r];     w0 = g_s2w[e * CAP + r];
            tok1 = g_s2t[e * CAP + r + 8]; w1 = g_s2w[e * CAP + r + 8];
        }
#pragma unroll
        for (int ni = 0; ni < 4; ni++) {
            int cb = n0 + nb + ni * 8 + 2 * lc;
            float b0 = be[cb], b1 = be[cb + 1];
            float v0 = acc[mi][ni][0] + b0, v1 = acc[mi][ni][1] + b1;
            float v2 = acc[mi][ni][2] + b0, v3 = acc[mi][ni][3] + b1;
            if (PHASE1) {
                v0 = fmaxf(v0, 0.f); v1 = fmaxf(v1, 0.f);
                v2 = fmaxf(v2, 0.f); v3 = fmaxf(v3, 0.f);
                size_t s0 = (size_t)(e * CAP + r) * HDIM + cb;
                size_t s1 = (size_t)(e * CAP + r + 8) * HDIM + cb;
                __half2 h0 = __floats2half2_rn(v0, v1);
                __half2 h1 = __floats2half2_rn(v2, v3);
                __half2 l0 = __floats2half2_rn(v0 - __half2float(__low2half(h0)),
                                               v1 - __half2float(__high2half(h0)));
                __half2 l1 = __floats2half2_rn(v2 - __half2float(__low2half(h1)),
                                               v3 - __half2float(__high2half(h1)));
                *(__half2*)(H16P(g_hh_) + s0) = h0;
                *(__half2*)(H16P(g_hh_) + s1) = h1;
                *(__half2*)(H16P(g_hl_) + s0) = l0;
                *(__half2*)(H16P(g_hl_) + s1) = l1;
            } else {
                if (tok0 >= 0) {
                    float* o = out + (size_t)tok0 * DDIM + cb;
                    atomicAdd(o,     w0 * v0);
                    atomicAdd(o + 1, w0 * v1);
                }
                if (tok1 >= 0) {
                    float* o = out + (size_t)tok1 * DDIM + cb;
                    atomicAdd(o,     w1 * v2);
                    atomicAdd(o + 1, w1 * v3);
                }
            }
        }
    }
}

// ---------------- aux loss ----------------
__global__ void aux_kernel(float* __restrict__ out, int out_size) {
    __shared__ float s[256];
    int tid = threadIdx.x;
    float p[NEXP];
#pragma unroll
    for (int e = 0; e < NEXP; e++) p[e] = 0.f;
    for (int i = tid; i < NTOK; i += 256)
#pragma unroll
        for (int e = 0; e < NEXP; e++) p[e] += g_scores[i * NEXP + e];

    float total = 0.f;
#pragma unroll
    for (int e = 0; e < NEXP; e++) {
        s[tid] = p[e];
        __syncthreads();
        for (int st = 128; st > 0; st >>= 1) {
            if (tid < st) s[tid] += s[tid + st];
            __syncthreads();
        }
        if (tid == 0) {
            float me = s[0] / (float)NTOK;
            float ce = (float)g_ce[e] / (float)NTOK;
            total += me * ce;
        }
        __syncthreads();
    }
    if (tid == 0) {
        float laux = (float)NEXP * total;
        for (long i = (long)NTOK * DDIM; i < (long)out_size; i++) out[i] = laux;
    }
}

// ---------------- launch ----------------
extern "C" void kernel_launch(void* const* d_in, const int* in_sizes, int n_in,
                              void* d_out, int out_size) {
    const float* x    = (const float*)d_in[0];
    const float* wg   = (const float*)d_in[1];
    const float* fc1w = (const float*)d_in[2];
    const float* fc1b = (const float*)d_in[3];
    const float* fc2w = (const float*)d_in[4];
    const float* fc2b = (const float*)d_in[5];
    float* out = (float*)d_out;
    (void)in_sizes; (void)n_in;

    cudaFuncSetAttribute(gemm_kernel<DDIM, HDIM, true >,
                         cudaFuncAttributeMaxDynamicSharedMemorySize, SMEM_DYN);
    cudaFuncSetAttribute(gemm_kernel<HDIM, DDIM, false>,
                         cudaFuncAttributeMaxDynamicSharedMemorySize, SMEM_DYN);

    init_kernel<<<(NTOK * DDIM / 4 + 255) / 256, 256>>>(out);
    split_x_kernel<<<(NTOK * DDIM / 2 + 255) / 256, 256>>>(x);
    tsplit_kernel<true ><<<dim3(HDIM / 32, DDIM / 32, NEXP), 256>>>(fc1w, DDIM, HDIM);
    tsplit_kernel<false><<<dim3(DDIM / 32, HDIM / 32, NEXP), 256>>>(fc2w, HDIM, DDIM);
    gate_kernel<<<NTOK / 8, 256>>>(x, wg);
    route_kernel<<<1, 512>>>();
    gemm_kernel<DDIM, HDIM, true ><<<dim3(HDIM / BN, CAP / BM, NEXP), 256, SMEM_DYN>>>(fc1b, out);
    gemm_kernel<HDIM, DDIM, false><<<dim3(DDIM / BN, CAP / BM, NEXP), 256, SMEM_DYN>>>(fc2b, out);
    aux_kernel<<<1, 256>>>(out, out_size);
}

// round 16
// speedup vs baseline: 1.6400x; 1.6030x over previous
#include <cuda_runtime.h>
#include <cuda_bf16.h>
#include <cuda_fp16.h>
#include <cstdint>

// Problem constants
#define NTOK 8192
#define DDIM 1024
#define HDIM 4096
#define NEXP 8
#define TOPK 2
#define CAP  2048          // (TOPK*NTOK)/NEXP
#define SLOTS (TOPK*NTOK)  // 16384

// ---------------- scratch (__device__ globals: allocation-free) ----------------
__device__ float g_scores[NTOK * NEXP];
__device__ float g_topv[NTOK * TOPK];
__device__ int   g_topi[NTOK * TOPK];
__device__ int   g_pos[SLOTS];
__device__ int   g_s2t[NEXP * CAP];
__device__ float g_s2w[NEXP * CAP];     // gate weight per expert slot
__device__ int   g_ce[NEXP];
// fp16 operands; uint4 backing guarantees 16B alignment
__device__ uint4 g_xh_[(size_t)NTOK * DDIM / 8];          // fp16(x)
__device__ uint4 g_w1h_[(size_t)NEXP * HDIM * DDIM / 8];  // [E][n=H][k=D] fp16(w1)
__device__ uint4 g_w2h_[(size_t)NEXP * DDIM * HDIM / 8];  // [E][n=D][k=H] fp16(w2)
__device__ uint4 g_hh_[(size_t)NEXP * CAP * HDIM / 8];    // fp16(h)

#define H16P(a) (( __half*)(a))
#define CH16P(a) ((const __half*)(a))

// ---------------- init: s2t/ce reset + zero out[0 .. N*D) ----------------
__global__ void init_kernel(float* __restrict__ out) {
    int i = blockIdx.x * blockDim.x + threadIdx.x;
    if (i < NEXP * CAP) g_s2t[i] = -1;
    if (i < NEXP)       g_ce[i]  = 0;
    if (i < NTOK * DDIM / 4)
        ((float4*)out)[i] = make_float4(0.f, 0.f, 0.f, 0.f);
}

// ---------------- convert x -> fp16 ----------------
__global__ void conv_x_kernel(const float* __restrict__ x) {
    int i = blockIdx.x * blockDim.x + threadIdx.x;
    const int NP = NTOK * DDIM / 2;
    if (i >= NP) return;
    float2 v = ((const float2*)x)[i];
    ((__half2*)g_xh_)[i] = __floats2half2_rn(v.x, v.y);
}

// ---------------- transpose + convert weights: in [E][K][N] -> out [E][N][K] fp16 ----------------
template<bool IS_W1>
__global__ void tsplit_kernel(const float* __restrict__ in, int K, int N) {
    __half* oh = H16P(IS_W1 ? g_w1h_ : g_w2h_);
    __shared__ float t[32][33];
    int e = blockIdx.z;
    int n0 = blockIdx.x * 32, k0 = blockIdx.y * 32;
    const float* ine = in + (size_t)e * K * N;
    int tid = threadIdx.x;
#pragma unroll
    for (int i = 0; i < 4; i++) {
        int idx = tid + i * 256;
        int k = idx >> 5, n = idx & 31;
        t[k][n] = ine[(size_t)(k0 + k) * N + n0 + n];
    }
    __syncthreads();
    size_t ob = (size_t)e * N * K;
#pragma unroll
    for (int i = 0; i < 2; i++) {
        int idx = tid + i * 256;
        int n = idx >> 4;
        int kp = idx & 15;
        int k = 2 * kp;
        __half2 v = __floats2half2_rn(t[k][n], t[k + 1][n]);
        *(__half2*)(oh + ob + (size_t)(n0 + n) * K + k0 + k) = v;
    }
}

// ---------------- gate ----------------
__global__ void gate_kernel(const float* __restrict__ x, const float* __restrict__ wg) {
    int gwarp = (blockIdx.x * blockDim.x + threadIdx.x) >> 5;
    int lane  = threadIdx.x & 31;
    if (gwarp >= NTOK) return;
    const float* xr = x + (size_t)gwarp * DDIM;
    float acc[NEXP];
#pragma unroll
    for (int e = 0; e < NEXP; e++) acc[e] = 0.f;
#pragma unroll 4
    for (int i = 0; i < DDIM / 32; i++) {
        int d = lane + 32 * i;
        float xv = xr[d];
        const float* wr = wg + d * NEXP;
#pragma unroll
        for (int e = 0; e < NEXP; e++) acc[e] = fmaf(xv, wr[e], acc[e]);
    }
#pragma unroll
    for (int off = 16; off > 0; off >>= 1)
#pragma unroll
        for (int e = 0; e < NEXP; e++)
            acc[e] += __shfl_xor_sync(0xffffffffu, acc[e], off);

    if (lane == 0) {
        float m = acc[0];
#pragma unroll
        for (int e = 1; e < NEXP; e++) m = fmaxf(m, acc[e]);
        float p[NEXP]; float s = 0.f;
#pragma unroll
        for (int e = 0; e < NEXP; e++) { p[e] = expf(acc[e] - m); s += p[e]; }
        float inv = 1.f / s;
#pragma unroll
        for (int e = 0; e < NEXP; e++) { p[e] *= inv; g_scores[gwarp * NEXP + e] = p[e]; }
        int i1 = 0; float v1 = p[0];
#pragma unroll
        for (int e = 1; e < NEXP; e++) if (p[e] > v1) { v1 = p[e]; i1 = e; }
        int i2 = -1; float v2 = -1.f;
#pragma unroll
        for (int e = 0; e < NEXP; e++) if (e != i1 && p[e] > v2) { v2 = p[e]; i2 = e; }
        g_topv[gwarp * 2 + 0] = v1; g_topv[gwarp * 2 + 1] = v2;
        g_topi[gwarp * 2 + 0] = i1; g_topi[gwarp * 2 + 1] = i2;
        atomicAdd(&g_ce[i1], 1);
    }
}

// ---------------- routing ----------------
__global__ void route_kernel() {
    const int T = 512, PER = SLOTS / T;
    int t = threadIdx.x;
    int lane = t & 31, w = t >> 5;
    int base = t * PER;

    int cnt[NEXP];
#pragma unroll
    for (int e = 0; e < NEXP; e++) cnt[e] = 0;
    int myexp[PER];
#pragma unroll
    for (int i = 0; i < PER; i++) {
        int s = base + i;
        int slot = s >> 13;
        int n = s & (NTOK - 1);
        int e = g_topi[n * 2 + slot];
        myexp[i] = e;
        cnt[e]++;
    }
    int inc[NEXP];
#pragma unroll
    for (int e = 0; e < NEXP; e++) inc[e] = cnt[e];
#pragma unroll
    for (int o = 1; o < 32; o <<= 1) {
#pragma unroll
        for (int e = 0; e < NEXP; e++) {
            int v = __shfl_up_sync(0xffffffffu, inc[e], o);
            if (lane >= o) inc[e] += v;
        }
    }
    __shared__ int wtot[16][NEXP], wexcl[16][NEXP];
    if (lane == 31)
#pragma unroll
        for (int e = 0; e < NEXP; e++) wtot[w][e] = inc[e];
    __syncthreads();
    if (t == 0) {
        int run[NEXP];
#pragma unroll
        for (int e = 0; e < NEXP; e++) run[e] = 0;
        for (int ww = 0; ww < 16; ww++)
#pragma unroll
            for (int e = 0; e < NEXP; e++) { wexcl[ww][e] = run[e]; run[e] += wtot[ww][e]; }
    }
    __syncthreads();
    int off[NEXP];
#pragma unroll
    for (int e = 0; e < NEXP; e++) off[e] = wexcl[w][e] + inc[e] - cnt[e];
#pragma unroll
    for (int i = 0; i < PER; i++) {
        int e = myexp[i];
        int p = off[e]++;
        int s = base + i;
        g_pos[s] = p;
        if (p < CAP) {
            int slot = s >> 13;
            int n = s & (NTOK - 1);
            g_s2t[e * CAP + p] = n;
            g_s2w[e * CAP + p] = g_topv[n * 2 + slot];
        }
    }
}

// ---------------- fp16 single-pass GEMM: 128x128 tile, BK=32, ldmatrix, 2-stage ----------------
#define BM 128
#define BN 128
#define BK 32
#define RPW 20   // uint32 words per row: 16 data (32 fp16) + 4 pad (pitch 80B, conflict-free LDSM)
#define TSTRIDE (128 * RPW * 4)          // 10240 B per tensor-stage
#define A_OFF(s) ((uint32_t)((s) * TSTRIDE))
#define B_OFF(s) ((uint32_t)(2 * TSTRIDE + (s) * TSTRIDE))
#define SMEM_DYN (4 * TSTRIDE)           // 40960 B

__device__ __forceinline__ void cp16(uint32_t dst, const void* src, int bytes) {
    asm volatile("cp.async.cg.shared.global [%0], [%1], 16, %2;\n"
                 :: "r"(dst), "l"(src), "r"(bytes));
}
__device__ __forceinline__ void cp_commit() { asm volatile("cp.async.commit_group;\n" ::); }
__device__ __forceinline__ void cp_wait1()  { asm volatile("cp.async.wait_group 1;\n" ::); }
__device__ __forceinline__ void cp_wait0()  { asm volatile("cp.async.wait_group 0;\n" ::); }

__device__ __forceinline__ void mma_f16(float* d, const uint32_t* a, const uint32_t* b) {
    asm volatile(
        "mma.sync.aligned.m16n8k16.row.col.f32.f16.f16.f32 "
        "{%0,%1,%2,%3}, {%4,%5,%6,%7}, {%8,%9}, {%0,%1,%2,%3};\n"
        : "+f"(d[0]), "+f"(d[1]), "+f"(d[2]), "+f"(d[3])
        : "r"(a[0]), "r"(a[1]), "r"(a[2]), "r"(a[3]), "r"(b[0]), "r"(b[1]));
}
__device__ __forceinline__ void ldsm4(uint32_t* r, uint32_t addr) {
    asm volatile("ldmatrix.sync.aligned.m8n8.x4.shared.b16 {%0,%1,%2,%3}, [%4];"
                 : "=r"(r[0]), "=r"(r[1]), "=r"(r[2]), "=r"(r[3]) : "r"(addr));
}

// PHASE1: A = gather(fp16 x), B = fp16(w1) [E][H][D]; out g_hh_ (relu+bias)
// PHASE2: A = g_hh_,          B = fp16(w2) [E][D][H]; epilogue scatter-atomicAdd into out
template<int KD, int ND, bool PHASE1>
__global__ void __launch_bounds__(256, 2) gemm_kernel(const float* __restrict__ bias,
                                                      float* __restrict__ out)
{
    extern __shared__ char smraw[];
    const uint32_t sbase = (uint32_t)__cvta_generic_to_shared(smraw);
    const int e  = blockIdx.z;
    const int m0 = blockIdx.y * BM;
    const int n0 = blockIdx.x * BN;
    const float* be = bias + (size_t)e * ND;
    const int tid = threadIdx.x;

    // ---- loader: 512 chunks of 16B per tensor per stage; 2 per thread ----
    const __half *asrc[2], *bsrc[2];
    int aok[2]; uint32_t sdst[2];
#pragma unroll
    for (int i = 0; i < 2; i++) {
        int c = tid + i * 256;
        int row = c >> 2, g = c & 3;
        sdst[i] = (uint32_t)(row * 80 + g * 16);
        if (PHASE1) {
            int tok = g_s2t[e * CAP + m0 + row];
            aok[i] = (tok >= 0) ? 16 : 0;
            size_t ao = (tok >= 0) ? ((size_t)tok * KD + g * 8) : 0;
            asrc[i] = CH16P(g_xh_) + ao;
        } else {
            aok[i] = 16;
            asrc[i] = CH16P(g_hh_) + (size_t)(e * CAP + m0 + row) * KD + g * 8;
        }
        size_t bo = (size_t)e * ND * KD + (size_t)(n0 + row) * KD + g * 8;
        bsrc[i] = CH16P(PHASE1 ? g_w1h_ : g_w2h_) + bo;
    }

    auto load_stage = [&](int buf, int kt) {
        size_t ko = (size_t)kt * BK;
#pragma unroll
        for (int i = 0; i < 2; i++) {
            cp16(sbase + A_OFF(buf) + sdst[i], asrc[i] + ko, aok[i]);
            cp16(sbase + B_OFF(buf) + sdst[i], bsrc[i] + ko, 16);
        }
        cp_commit();
    };

    // ---- warp tiling: 2x4 warps, each 64x32 ----
    const int warp = tid >> 5, lane = tid & 31;
    const int wm = warp >> 2, wn = warp & 3;
    const int mb = wm * 64, nb = wn * 32;
    const int lr = lane >> 2, lc = lane & 3;

    const uint32_t a_lane = (uint32_t)((mb + (lane & 15)) * 80 + ((lane >> 4) & 1) * 16);
    const uint32_t b_lane0 = (uint32_t)((nb + ((lane >> 4) & 1) * 8 + (lane & 7)) * 80
                                        + ((lane >> 3) & 1) * 16);

    float acc[4][4][4];
#pragma unroll
    for (int mi = 0; mi < 4; mi++)
#pragma unroll
        for (int ni = 0; ni < 4; ni++)
#pragma unroll
            for (int r = 0; r < 4; r++) acc[mi][ni][r] = 0.f;

    const int KT = KD / BK;
    load_stage(0, 0);

    for (int kt = 0; kt < KT; kt++) {
        int buf = kt & 1;
        if (kt + 1 < KT) { load_stage(buf ^ 1, kt + 1); cp_wait1(); }
        else             { cp_wait0(); }
        __syncthreads();

        const uint32_t a_s = sbase + A_OFF(buf);
        const uint32_t b_s = sbase + B_OFF(buf);

#pragma unroll
        for (int ks = 0; ks < 2; ks++) {
            const uint32_t ksb = (uint32_t)(ks * 32);
            uint32_t bh[4][2];
            ldsm4(&bh[0][0], b_s + ksb + b_lane0);
            ldsm4(&bh[2][0], b_s + ksb + b_lane0 + 16 * 80);
            uint32_t af[4][4];
#pragma unroll
            for (int mi = 0; mi < 4; mi++)
                ldsm4(af[mi], a_s + ksb + a_lane + (uint32_t)(mi * 16 * 80));
#pragma unroll
            for (int mi = 0; mi < 4; mi++)
#pragma unroll
                for (int ni = 0; ni < 4; ni++)
                    mma_f16(acc[mi][ni], af[mi], bh[ni]);
        }
        __syncthreads();
    }

    // ---- epilogue ----
#pragma unroll
    for (int mi = 0; mi < 4; mi++) {
        int r = m0 + mb + mi * 16 + lr;       // row within expert buffer
        int tok0 = 0, tok1 = 0; float w0 = 0.f, w1 = 0.f;
        if (!PHASE1) {
            tok0 = g_s2t[e * CAP + r];     w0 = g_s2w[e * CAP + r];
            tok1 = g_s2t[e * CAP + r + 8]; w1 = g_s2w[e * CAP + r + 8];
        }
#pragma unroll
        for (int ni = 0; ni < 4; ni++) {
            int cb = n0 + nb + ni * 8 + 2 * lc;
            float b0 = be[cb], b1 = be[cb + 1];
            float v0 = acc[mi][ni][0] + b0, v1 = acc[mi][ni][1] + b1;
            float v2 = acc[mi][ni][2] + b0, v3 = acc[mi][ni][3] + b1;
            if (PHASE1) {
                v0 = fmaxf(v0, 0.f); v1 = fmaxf(v1, 0.f);
                v2 = fmaxf(v2, 0.f); v3 = fmaxf(v3, 0.f);
                size_t s0 = (size_t)(e * CAP + r) * HDIM + cb;
                size_t s1 = (size_t)(e * CAP + r + 8) * HDIM + cb;
                *(__half2*)(H16P(g_hh_) + s0) = __floats2half2_rn(v0, v1);
                *(__half2*)(H16P(g_hh_) + s1) = __floats2half2_rn(v2, v3);
            } else {
                if (tok0 >= 0) {
                    float* o = out + (size_t)tok0 * DDIM + cb;
                    atomicAdd(o,     w0 * v0);
                    atomicAdd(o + 1, w0 * v1);
                }
                if (tok1 >= 0) {
                    float* o = out + (size_t)tok1 * DDIM + cb;
                    atomicAdd(o,     w1 * v2);
                    atomicAdd(o + 1, w1 * v3);
                }
            }
        }
    }
}

// ---------------- aux loss ----------------
__global__ void aux_kernel(float* __restrict__ out, int out_size) {
    __shared__ float s[256];
    int tid = threadIdx.x;
    float p[NEXP];
#pragma unroll
    for (int e = 0; e < NEXP; e++) p[e] = 0.f;
    for (int i = tid; i < NTOK; i += 256)
#pragma unroll
        for (int e = 0; e < NEXP; e++) p[e] += g_scores[i * NEXP + e];

    float total = 0.f;
#pragma unroll
    for (int e = 0; e < NEXP; e++) {
        s[tid] = p[e];
        __syncthreads();
        for (int st = 128; st > 0; st >>= 1) {
            if (tid < st) s[tid] += s[tid + st];
            __syncthreads();
        }
        if (tid == 0) {
            float me = s[0] / (float)NTOK;
            float ce = (float)g_ce[e] / (float)NTOK;
            total += me * ce;
        }
        __syncthreads();
    }
    if (tid == 0) {
        float laux = (float)NEXP * total;
        for (long i = (long)NTOK * DDIM; i < (long)out_size; i++) out[i] = laux;
    }
}

// ---------------- launch ----------------
extern "C" void kernel_launch(void* const* d_in, const int* in_sizes, int n_in,
                              void* d_out, int out_size) {
    const float* x    = (const float*)d_in[0];
    const float* wg   = (const float*)d_in[1];
    const float* fc1w = (const float*)d_in[2];
    const float* fc1b = (const float*)d_in[3];
    const float* fc2w = (const float*)d_in[4];
    const float* fc2b = (const float*)d_in[5];
    float* out = (float*)d_out;
    (void)in_sizes; (void)n_in;

    cudaFuncSetAttribute(gemm_kernel<DDIM, HDIM, true >,
                         cudaFuncAttributeMaxDynamicSharedMemorySize, SMEM_DYN);
    cudaFuncSetAttribute(gemm_kernel<HDIM, DDIM, false>,
                         cudaFuncAttributeMaxDynamicSharedMemorySize, SMEM_DYN);

    init_kernel<<<(NTOK * DDIM / 4 + 255) / 256, 256>>>(out);
    conv_x_kernel<<<(NTOK * DDIM / 2 + 255) / 256, 256>>>(x);
    tsplit_kernel<true ><<<dim3(HDIM / 32, DDIM / 32, NEXP), 256>>>(fc1w, DDIM, HDIM);
    tsplit_kernel<false><<<dim3(DDIM / 32, HDIM / 32, NEXP), 256>>>(fc2w, HDIM, DDIM);
    gate_kernel<<<NTOK / 8, 256>>>(x, wg);
    route_kernel<<<1, 512>>>();
    gemm_kernel<DDIM, HDIM, true ><<<dim3(HDIM / BN, CAP / BM, NEXP), 256, SMEM_DYN>>>(fc1b, out);
    gemm_kernel<HDIM, DDIM, false><<<dim3(DDIM / BN, CAP / BM, NEXP), 256, SMEM_DYN>>>(fc2b, out);
    aux_kernel<<<1, 256>>>(out, out_size);
}

// round 17
// speedup vs baseline: 1.7658x; 1.0767x over previous
#include <cuda_runtime.h>
#include <cuda_bf16.h>
#include <cuda_fp16.h>
#include <cstdint>

// Problem constants
#define NTOK 8192
#define DDIM 1024
#define HDIM 4096
#define NEXP 8
#define TOPK 2
#define CAP  2048          // (TOPK*NTOK)/NEXP
#define SLOTS (TOPK*NTOK)  // 16384

// ---------------- scratch (__device__ globals: allocation-free) ----------------
__device__ float g_scores[NTOK * NEXP];
__device__ float g_topv[NTOK * TOPK];
__device__ int   g_topi[NTOK * TOPK];
__device__ int   g_pos[SLOTS];
__device__ int   g_s2t[NEXP * CAP];
__device__ float g_s2w[NEXP * CAP];     // gate weight per expert slot
__device__ int   g_ce[NEXP];
// fp16 operands; uint4 backing guarantees 16B alignment
__device__ uint4 g_xh_[(size_t)NTOK * DDIM / 8];          // fp16(x)
__device__ uint4 g_w1h_[(size_t)NEXP * HDIM * DDIM / 8];  // [E][n=H][k=D] fp16(w1)
__device__ uint4 g_w2h_[(size_t)NEXP * DDIM * HDIM / 8];  // [E][n=D][k=H] fp16(w2)
__device__ uint4 g_hh_[(size_t)NEXP * CAP * HDIM / 8];    // fp16(h)

#define H16P(a) (( __half*)(a))
#define CH16P(a) ((const __half*)(a))

// ---------------- init: s2t/ce reset + zero out[0 .. N*D) ----------------
__global__ void init_kernel(float* __restrict__ out) {
    int i = blockIdx.x * blockDim.x + threadIdx.x;
    if (i < NEXP * CAP) g_s2t[i] = -1;
    if (i < NEXP)       g_ce[i]  = 0;
    if (i < NTOK * DDIM / 4)
        ((float4*)out)[i] = make_float4(0.f, 0.f, 0.f, 0.f);
}

// ---------------- transpose + convert weights: in [E][K][N] -> out [E][N][K] fp16 ----------------
template<bool IS_W1>
__global__ void tsplit_kernel(const float* __restrict__ in, int K, int N) {
    __half* oh = H16P(IS_W1 ? g_w1h_ : g_w2h_);
    __shared__ float t[32][33];
    int e = blockIdx.z;
    int n0 = blockIdx.x * 32, k0 = blockIdx.y * 32;
    const float* ine = in + (size_t)e * K * N;
    int tid = threadIdx.x;
#pragma unroll
    for (int i = 0; i < 4; i++) {
        int idx = tid + i * 256;
        int k = idx >> 5, n = idx & 31;
        t[k][n] = ine[(size_t)(k0 + k) * N + n0 + n];
    }
    __syncthreads();
    size_t ob = (size_t)e * N * K;
#pragma unroll
    for (int i = 0; i < 2; i++) {
        int idx = tid + i * 256;
        int n = idx >> 4;
        int kp = idx & 15;
        int k = 2 * kp;
        __half2 v = __floats2half2_rn(t[k][n], t[k + 1][n]);
        *(__half2*)(oh + ob + (size_t)(n0 + n) * K + k0 + k) = v;
    }
}

// ---------------- gate (also emits fp16(x) into g_xh_) ----------------
__global__ void gate_kernel(const float* __restrict__ x, const float* __restrict__ wg) {
    int gwarp = (blockIdx.x * blockDim.x + threadIdx.x) >> 5;
    int lane  = threadIdx.x & 31;
    if (gwarp >= NTOK) return;
    const float* xr = x + (size_t)gwarp * DDIM;
    __half* xh = H16P(g_xh_) + (size_t)gwarp * DDIM;
    float acc[NEXP];
#pragma unroll
    for (int e = 0; e < NEXP; e++) acc[e] = 0.f;
#pragma unroll 4
    for (int i = 0; i < DDIM / 32; i++) {
        int d = lane + 32 * i;
        float xv = xr[d];
        xh[d] = __float2half_rn(xv);
        const float* wr = wg + d * NEXP;
#pragma unroll
        for (int e = 0; e < NEXP; e++) acc[e] = fmaf(xv, wr[e], acc[e]);
    }
#pragma unroll
    for (int off = 16; off > 0; off >>= 1)
#pragma unroll
        for (int e = 0; e < NEXP; e++)
            acc[e] += __shfl_xor_sync(0xffffffffu, acc[e], off);

    if (lane == 0) {
        float m = acc[0];
#pragma unroll
        for (int e = 1; e < NEXP; e++) m = fmaxf(m, acc[e]);
        float p[NEXP]; float s = 0.f;
#pragma unroll
        for (int e = 0; e < NEXP; e++) { p[e] = expf(acc[e] - m); s += p[e]; }
        float inv = 1.f / s;
#pragma unroll
        for (int e = 0; e < NEXP; e++) { p[e] *= inv; g_scores[gwarp * NEXP + e] = p[e]; }
        int i1 = 0; float v1 = p[0];
#pragma unroll
        for (int e = 1; e < NEXP; e++) if (p[e] > v1) { v1 = p[e]; i1 = e; }
        int i2 = -1; float v2 = -1.f;
#pragma unroll
        for (int e = 0; e < NEXP; e++) if (e != i1 && p[e] > v2) { v2 = p[e]; i2 = e; }
        g_topv[gwarp * 2 + 0] = v1; g_topv[gwarp * 2 + 1] = v2;
        g_topi[gwarp * 2 + 0] = i1; g_topi[gwarp * 2 + 1] = i2;
        atomicAdd(&g_ce[i1], 1);
    }
}

// ---------------- routing ----------------
__global__ void route_kernel() {
    const int T = 512, PER = SLOTS / T;
    int t = threadIdx.x;
    int lane = t & 31, w = t >> 5;
    int base = t * PER;

    int cnt[NEXP];
#pragma unroll
    for (int e = 0; e < NEXP; e++) cnt[e] = 0;
    int myexp[PER];
#pragma unroll
    for (int i = 0; i < PER; i++) {
        int s = base + i;
        int slot = s >> 13;
        int n = s & (NTOK - 1);
        int e = g_topi[n * 2 + slot];
        myexp[i] = e;
        cnt[e]++;
    }
    int inc[NEXP];
#pragma unroll
    for (int e = 0; e < NEXP; e++) inc[e] = cnt[e];
#pragma unroll
    for (int o = 1; o < 32; o <<= 1) {
#pragma unroll
        for (int e = 0; e < NEXP; e++) {
            int v = __shfl_up_sync(0xffffffffu, inc[e], o);
            if (lane >= o) inc[e] += v;
        }
    }
    __shared__ int wtot[16][NEXP], wexcl[16][NEXP];
    if (lane == 31)
#pragma unroll
        for (int e = 0; e < NEXP; e++) wtot[w][e] = inc[e];
    __syncthreads();
    if (t == 0) {
        int run[NEXP];
#pragma unroll
        for (int e = 0; e < NEXP; e++) run[e] = 0;
        for (int ww = 0; ww < 16; ww++)
#pragma unroll
            for (int e = 0; e < NEXP; e++) { wexcl[ww][e] = run[e]; run[e] += wtot[ww][e]; }
    }
    __syncthreads();
    int off[NEXP];
#pragma unroll
    for (int e = 0; e < NEXP; e++) off[e] = wexcl[w][e] + inc[e] - cnt[e];
#pragma unroll
    for (int i = 0; i < PER; i++) {
        int e = myexp[i];
        int p = off[e]++;
        int s = base + i;
        g_pos[s] = p;
        if (p < CAP) {
            int slot = s >> 13;
            int n = s & (NTOK - 1);
            g_s2t[e * CAP + p] = n;
            g_s2w[e * CAP + p] = g_topv[n * 2 + slot];
        }
    }
}

// ---------------- fp16 GEMM: 128x128 tile, BK=64, ldmatrix, 2-stage ----------------
#define BM 128
#define BN 128
#define BK 64
#define RPB 144  // row pitch bytes: 128 data (64 fp16) + 16 pad -> conflict-free LDSM (+4 bank walk)
#define TSTRIDE (128 * RPB)              // 18432 B per tensor-stage
#define A_OFF(s) ((uint32_t)((s) * TSTRIDE))
#define B_OFF(s) ((uint32_t)(2 * TSTRIDE + (s) * TSTRIDE))
#define SMEM_DYN (4 * TSTRIDE)           // 73728 B

__device__ __forceinline__ void cp16(uint32_t dst, const void* src, int bytes) {
    asm volatile("cp.async.cg.shared.global [%0], [%1], 16, %2;\n"
                 :: "r"(dst), "l"(src), "r"(bytes));
}
__device__ __forceinline__ void cp_commit() { asm volatile("cp.async.commit_group;\n" ::); }
__device__ __forceinline__ void cp_wait1()  { asm volatile("cp.async.wait_group 1;\n" ::); }
__device__ __forceinline__ void cp_wait0()  { asm volatile("cp.async.wait_group 0;\n" ::); }

__device__ __forceinline__ void mma_f16(float* d, const uint32_t* a, const uint32_t* b) {
    asm volatile(
        "mma.sync.aligned.m16n8k16.row.col.f32.f16.f16.f32 "
        "{%0,%1,%2,%3}, {%4,%5,%6,%7}, {%8,%9}, {%0,%1,%2,%3};\n"
        : "+f"(d[0]), "+f"(d[1]), "+f"(d[2]), "+f"(d[3])
        : "r"(a[0]), "r"(a[1]), "r"(a[2]), "r"(a[3]), "r"(b[0]), "r"(b[1]));
}
__device__ __forceinline__ void ldsm4(uint32_t* r, uint32_t addr) {
    asm volatile("ldmatrix.sync.aligned.m8n8.x4.shared.b16 {%0,%1,%2,%3}, [%4];"
                 : "=r"(r[0]), "=r"(r[1]), "=r"(r[2]), "=r"(r[3]) : "r"(addr));
}

// PHASE1: A = gather(fp16 x), B = fp16(w1) [E][H][D]; out g_hh_ (relu+bias)
// PHASE2: A = g_hh_,          B = fp16(w2) [E][D][H]; epilogue scatter-atomicAdd into out
template<int KD, int ND, bool PHASE1>
__global__ void __launch_bounds__(256, 2) gemm_kernel(const float* __restrict__ bias,
                                                      float* __restrict__ out)
{
    extern __shared__ char smraw[];
    const uint32_t sbase = (uint32_t)__cvta_generic_to_shared(smraw);
    const int e  = blockIdx.z;
    const int m0 = blockIdx.y * BM;
    const int n0 = blockIdx.x * BN;
    const float* be = bias + (size_t)e * ND;
    const int tid = threadIdx.x;

    // ---- loader: 1024 chunks of 16B per tensor per stage; 4 per thread ----
    // chunk c: row = c>>3 (0..127), g = c&7 -> elems g*8.., smem off row*144 + g*16
    const __half *asrc[4], *bsrc[4];
    int aok[4]; uint32_t sdst[4];
#pragma unroll
    for (int i = 0; i < 4; i++) {
        int c = tid + i * 256;
        int row = c >> 3, g = c & 7;
        sdst[i] = (uint32_t)(row * RPB + g * 16);
        if (PHASE1) {
            int tok = g_s2t[e * CAP + m0 + row];
            aok[i] = (tok >= 0) ? 16 : 0;
            size_t ao = (tok >= 0) ? ((size_t)tok * KD + g * 8) : 0;
            asrc[i] = CH16P(g_xh_) + ao;
        } else {
            aok[i] = 16;
            asrc[i] = CH16P(g_hh_) + (size_t)(e * CAP + m0 + row) * KD + g * 8;
        }
        size_t bo = (size_t)e * ND * KD + (size_t)(n0 + row) * KD + g * 8;
        bsrc[i] = CH16P(PHASE1 ? g_w1h_ : g_w2h_) + bo;
    }

    auto load_stage = [&](int buf, int kt) {
        size_t ko = (size_t)kt * BK;
#pragma unroll
        for (int i = 0; i < 4; i++) {
            cp16(sbase + A_OFF(buf) + sdst[i], asrc[i] + ko, aok[i]);
            cp16(sbase + B_OFF(buf) + sdst[i], bsrc[i] + ko, 16);
        }
        cp_commit();
    };

    // ---- warp tiling: 2x4 warps, each 64x32 ----
    const int warp = tid >> 5, lane = tid & 31;
    const int wm = warp >> 2, wn = warp & 3;
    const int mb = wm * 64, nb = wn * 32;
    const int lr = lane >> 2, lc = lane & 3;

    const uint32_t a_lane = (uint32_t)((mb + (lane & 15)) * RPB + ((lane >> 4) & 1) * 16);
    const uint32_t b_lane0 = (uint32_t)((nb + ((lane >> 4) & 1) * 8 + (lane & 7)) * RPB
                                        + ((lane >> 3) & 1) * 16);

    float acc[4][4][4];
#pragma unroll
    for (int mi = 0; mi < 4; mi++)
#pragma unroll
        for (int ni = 0; ni < 4; ni++)
#pragma unroll
            for (int r = 0; r < 4; r++) acc[mi][ni][r] = 0.f;

    const int KT = KD / BK;
    load_stage(0, 0);

    for (int kt = 0; kt < KT; kt++) {
        int buf = kt & 1;
        if (kt + 1 < KT) { load_stage(buf ^ 1, kt + 1); cp_wait1(); }
        else             { cp_wait0(); }
        __syncthreads();

        const uint32_t a_s = sbase + A_OFF(buf);
        const uint32_t b_s = sbase + B_OFF(buf);

#pragma unroll
        for (int ks = 0; ks < 4; ks++) {
            const uint32_t ksb = (uint32_t)(ks * 32);    // 16 fp16 = 32 B per k-step
            uint32_t bh[4][2];
            ldsm4(&bh[0][0], b_s + ksb + b_lane0);
            ldsm4(&bh[2][0], b_s + ksb + b_lane0 + 16 * RPB);
            uint32_t af[4][4];
#pragma unroll
            for (int mi = 0; mi < 4; mi++)
                ldsm4(af[mi], a_s + ksb + a_lane + (uint32_t)(mi * 16 * RPB));
#pragma unroll
            for (int mi = 0; mi < 4; mi++)
#pragma unroll
                for (int ni = 0; ni < 4; ni++)
                    mma_f16(acc[mi][ni], af[mi], bh[ni]);
        }
        __syncthreads();
    }

    // ---- epilogue ----
#pragma unroll
    for (int mi = 0; mi < 4; mi++) {
        int r = m0 + mb + mi * 16 + lr;       // row within expert buffer
        int tok0 = 0, tok1 = 0; float w0 = 0.f, w1 = 0.f;
        if (!PHASE1) {
            tok0 = g_s2t[e * CAP + r];     w0 = g_s2w[e * CAP + r];
            tok1 = g_s2t[e * CAP + r + 8]; w1 = g_s2w[e * CAP + r + 8];
        }
#pragma unroll
        for (int ni = 0; ni < 4; ni++) {
            int cb = n0 + nb + ni * 8 + 2 * lc;
            float b0 = be[cb], b1 = be[cb + 1];
            float v0 = acc[mi][ni][0] + b0, v1 = acc[mi][ni][1] + b1;
            float v2 = acc[mi][ni][2] + b0, v3 = acc[mi][ni][3] + b1;
            if (PHASE1) {
                v0 = fmaxf(v0, 0.f); v1 = fmaxf(v1, 0.f);
                v2 = fmaxf(v2, 0.f); v3 = fmaxf(v3, 0.f);
                size_t s0 = (size_t)(e * CAP + r) * HDIM + cb;
                size_t s1 = (size_t)(e * CAP + r + 8) * HDIM + cb;
                *(__half2*)(H16P(g_hh_) + s0) = __floats2half2_rn(v0, v1);
                *(__half2*)(H16P(g_hh_) + s1) = __floats2half2_rn(v2, v3);
            } else {
                if (tok0 >= 0) {
                    float* o = out + (size_t)tok0 * DDIM + cb;
                    atomicAdd(o,     w0 * v0);
                    atomicAdd(o + 1, w0 * v1);
                }
                if (tok1 >= 0) {
                    float* o = out + (size_t)tok1 * DDIM + cb;
                    atomicAdd(o,     w1 * v2);
                    atomicAdd(o + 1, w1 * v3);
                }
            }
        }
    }
}

// ---------------- aux loss ----------------
__global__ void aux_kernel(float* __restrict__ out, int out_size) {
    __shared__ float s[256];
    int tid = threadIdx.x;
    float p[NEXP];
#pragma unroll
    for (int e = 0; e < NEXP; e++) p[e] = 0.f;
    for (int i = tid; i < NTOK; i += 256)
#pragma unroll
        for (int e = 0; e < NEXP; e++) p[e] += g_scores[i * NEXP + e];

    float total = 0.f;
#pragma unroll
    for (int e = 0; e < NEXP; e++) {
        s[tid] = p[e];
        __syncthreads();
        for (int st = 128; st > 0; st >>= 1) {
            if (tid < st) s[tid] += s[tid + st];
            __syncthreads();
        }
        if (tid == 0) {
            float me = s[0] / (float)NTOK;
            float ce = (float)g_ce[e] / (float)NTOK;
            total += me * ce;
        }
        __syncthreads();
    }
    if (tid == 0) {
        float laux = (float)NEXP * total;
        for (long i = (long)NTOK * DDIM; i < (long)out_size; i++) out[i] = laux;
    }
}

// ---------------- launch ----------------
extern "C" void kernel_launch(void* const* d_in, const int* in_sizes, int n_in,
                              void* d_out, int out_size) {
    const float* x    = (const float*)d_in[0];
    const float* wg   = (const float*)d_in[1];
    const float* fc1w = (const float*)d_in[2];
    const float* fc1b = (const float*)d_in[3];
    const float* fc2w = (const float*)d_in[4];
    const float* fc2b = (const float*)d_in[5];
    float* out = (float*)d_out;
    (void)in_sizes; (void)n_in;

    cudaFuncSetAttribute(gemm_kernel<DDIM, HDIM, true >,
                         cudaFuncAttributeMaxDynamicSharedMemorySize, SMEM_DYN);
    cudaFuncSetAttribute(gemm_kernel<HDIM, DDIM, false>,
                         cudaFuncAttributeMaxDynamicSharedMemorySize, SMEM_DYN);

    init_kernel<<<(NTOK * DDIM / 4 + 255) / 256, 256>>>(out);
    gate_kernel<<<NTOK / 8, 256>>>(x, wg);
    tsplit_kernel<true ><<<dim3(HDIM / 32, DDIM / 32, NEXP), 256>>>(fc1w, DDIM, HDIM);
    tsplit_kernel<false><<<dim3(DDIM / 32, HDIM / 32, NEXP), 256>>>(fc2w, HDIM, DDIM);
    route_kernel<<<1, 512>>>();
    gemm_kernel<DDIM, HDIM, true ><<<dim3(HDIM / BN, CAP / BM, NEXP), 256, SMEM_DYN>>>(fc1b, out);
    gemm_kernel<HDIM, DDIM, false><<<dim3(DDIM / BN, CAP / BM, NEXP), 256, SMEM_DYN>>>(fc2b, out);
    aux_kernel<<<1, 256>>>(out, out_size);
}